// round 2
// baseline (speedup 1.0000x reference)
#include <cuda_runtime.h>
#include <math.h>

#define D_HID 512
#define SEQ   1024
#define BATCH 16
#define NHEAD 8
#define DHEAD 64
#define PFD   2048
#define MROWS (BATCH*SEQ)   /* 16384 */

#define SZ_MAT ((size_t)MROWS * D_HID)   /* 8,388,608 floats = 32MB */
#define SZ_H   ((size_t)MROWS * PFD)     /* 33,554,432 floats = 128MB */

// ---------------- scratch (static device globals; no allocation) ----------------
// Buffer reuse plan:
//   g_q, g_k, g_v : QKV projections (live until end of flash_attn)
//   g_ctx         : attention output; also reused later as x2 (LN2 out)
//   g_k reused as sa (wo projection output)  [k dead after attention]
//   g_x1          : LN1 output (live through pf2)
//   g_hid         : FFN hidden 2048-wide
//   g_v reused as ff (pf2 output)            [v dead after attention]
__device__ float g_q[SZ_MAT];
__device__ float g_k[SZ_MAT];
__device__ float g_v[SZ_MAT];
__device__ float g_ctx[SZ_MAT];
__device__ float g_x1[SZ_MAT];
__device__ float g_hid[SZ_H];
__device__ float g_norms[MROWS];
__device__ float g_pooled[BATCH * D_HID];

// ---------------- SGEMM: C[M,N] = A[M,K] @ W[N,K]^T + bias, optional ReLU ------
// BM=BN=128, BK=8, 256 threads, 8x8 per thread.
__global__ __launch_bounds__(256, 2) void sgemm_bias(
    const float* __restrict__ A, const float* __restrict__ W,
    const float* __restrict__ bias, float* __restrict__ C,
    int M, int N, int K, int doRelu)
{
    __shared__ float As[8][128];
    __shared__ float Bs[8][128];
    const int tid  = threadIdx.x;
    const int brow = blockIdx.y, bcol = blockIdx.x;
    const int tr = tid >> 4, tc = tid & 15;
    const int loadRow = tid >> 1;
    const int loadCol = (tid & 1) << 2;
    const float* Ab = A + (size_t)brow * 128 * K;
    const float* Wb = W + (size_t)bcol * 128 * K;

    float acc[8][8];
#pragma unroll
    for (int i = 0; i < 8; i++)
#pragma unroll
        for (int j = 0; j < 8; j++) acc[i][j] = 0.f;

    for (int k0 = 0; k0 < K; k0 += 8) {
        float4 a4 = *(const float4*)(Ab + (size_t)loadRow * K + k0 + loadCol);
        float4 b4 = *(const float4*)(Wb + (size_t)loadRow * K + k0 + loadCol);
        __syncthreads();
        As[loadCol + 0][loadRow] = a4.x; As[loadCol + 1][loadRow] = a4.y;
        As[loadCol + 2][loadRow] = a4.z; As[loadCol + 3][loadRow] = a4.w;
        Bs[loadCol + 0][loadRow] = b4.x; Bs[loadCol + 1][loadRow] = b4.y;
        Bs[loadCol + 2][loadRow] = b4.z; Bs[loadCol + 3][loadRow] = b4.w;
        __syncthreads();
#pragma unroll
        for (int kk = 0; kk < 8; kk++) {
            float ra[8], rb[8];
            *(float4*)(ra)     = *(const float4*)(&As[kk][tr * 8]);
            *(float4*)(ra + 4) = *(const float4*)(&As[kk][tr * 8 + 4]);
            *(float4*)(rb)     = *(const float4*)(&Bs[kk][tc * 8]);
            *(float4*)(rb + 4) = *(const float4*)(&Bs[kk][tc * 8 + 4]);
#pragma unroll
            for (int i = 0; i < 8; i++)
#pragma unroll
                for (int j = 0; j < 8; j++) acc[i][j] += ra[i] * rb[j];
        }
    }

    float bb[8];
#pragma unroll
    for (int j = 0; j < 8; j++) bb[j] = bias[bcol * 128 + tc * 8 + j];
#pragma unroll
    for (int i = 0; i < 8; i++) {
        int row = brow * 128 + tr * 8 + i;
        float out[8];
#pragma unroll
        for (int j = 0; j < 8; j++) {
            float v = acc[i][j] + bb[j];
            out[j] = doRelu ? fmaxf(v, 0.f) : v;
        }
        float* cp = C + (size_t)row * N + bcol * 128 + tc * 8;
        *(float4*)cp       = *(float4*)out;
        *(float4*)(cp + 4) = *(float4*)(out + 4);
    }
}

// ---------------- Flash attention: BQ=64, BKV=32, dh=64, fp32 ------------------
// grid: (qTiles=16, heads=8, batch=16), 256 threads.
// Thread t owns q-row r = t/4 and dims d = (t&3) + 4*i, i in [0,16).
__global__ __launch_bounds__(256) void flash_attn(
    const float* __restrict__ Q, const float* __restrict__ Kg,
    const float* __restrict__ Vg, float* __restrict__ O)
{
    __shared__ float qs[64][65];
    __shared__ float ks[32][65];
    __shared__ float vs[32][65];
    __shared__ float ss[64][33];
    __shared__ float m_s[64], l_s[64], alpha_s[64];

    const int tid = threadIdx.x;
    const int qt = blockIdx.x, hh = blockIdx.y, b = blockIdx.z;
    const size_t base = ((size_t)b * SEQ) * D_HID + hh * DHEAD;

    // load Q tile (64x64)
#pragma unroll
    for (int rp = 0; rp < 4; rp++) {
        int f = tid + rp * 256;          // float4 index 0..1023
        int row = f >> 4, c4 = f & 15;
        float4 v4 = *(const float4*)(Q + base + (size_t)(qt * 64 + row) * D_HID + c4 * 4);
        qs[row][c4 * 4 + 0] = v4.x; qs[row][c4 * 4 + 1] = v4.y;
        qs[row][c4 * 4 + 2] = v4.z; qs[row][c4 * 4 + 3] = v4.w;
    }
    if (tid < 64) { m_s[tid] = -1e30f; l_s[tid] = 0.f; }

    float acc[16];
#pragma unroll
    for (int i = 0; i < 16; i++) acc[i] = 0.f;

    const int r = tid >> 2;
    const int dl = tid & 3;

    for (int kt = 0; kt < SEQ / 32; kt++) {
        __syncthreads();
        // load K,V tiles (32x64 each)
#pragma unroll
        for (int rp = 0; rp < 2; rp++) {
            int f = tid + rp * 256;      // 0..511
            int row = f >> 4, c4 = f & 15;
            size_t goff = base + (size_t)(kt * 32 + row) * D_HID + c4 * 4;
            float4 kv = *(const float4*)(Kg + goff);
            float4 vv = *(const float4*)(Vg + goff);
            ks[row][c4 * 4 + 0] = kv.x; ks[row][c4 * 4 + 1] = kv.y;
            ks[row][c4 * 4 + 2] = kv.z; ks[row][c4 * 4 + 3] = kv.w;
            vs[row][c4 * 4 + 0] = vv.x; vs[row][c4 * 4 + 1] = vv.y;
            vs[row][c4 * 4 + 2] = vv.z; vs[row][c4 * 4 + 3] = vv.w;
        }
        __syncthreads();

        // phase 1: scores. thread -> row r, cols j0..j0+8
        {
            const int j0 = dl * 8;
            float sreg[8];
#pragma unroll
            for (int jj = 0; jj < 8; jj++) sreg[jj] = 0.f;
            for (int d = 0; d < 64; d++) {
                float qv = qs[r][d];
#pragma unroll
                for (int jj = 0; jj < 8; jj++) sreg[jj] += qv * ks[j0 + jj][d];
            }
#pragma unroll
            for (int jj = 0; jj < 8; jj++) ss[r][j0 + jj] = sreg[jj] * 0.125f;
        }
        __syncthreads();

        // phase 2: per-row online softmax (64 threads)
        if (tid < 64) {
            float m_old = m_s[tid];
            float mt = m_old;
#pragma unroll
            for (int j = 0; j < 32; j++) mt = fmaxf(mt, ss[tid][j]);
            float alpha = expf(m_old - mt);
            float lsum = 0.f;
#pragma unroll
            for (int j = 0; j < 32; j++) {
                float p = expf(ss[tid][j] - mt);
                ss[tid][j] = p;
                lsum += p;
            }
            l_s[tid] = l_s[tid] * alpha + lsum;
            m_s[tid] = mt;
            alpha_s[tid] = alpha;
        }
        __syncthreads();

        // phase 3: rescale + accumulate P@V
        {
            float al = alpha_s[r];
#pragma unroll
            for (int i = 0; i < 16; i++) acc[i] *= al;
            for (int j = 0; j < 32; j++) {
                float p = ss[r][j];
#pragma unroll
                for (int i = 0; i < 16; i++) acc[i] += p * vs[j][dl + 4 * i];
            }
        }
    }
    __syncthreads();
    float linv = 1.0f / l_s[r];
#pragma unroll
    for (int i = 0; i < 16; i++)
        O[base + (size_t)(qt * 64 + r) * D_HID + dl + 4 * i] = acc[i] * linv;
}

// ---------------- residual + LayerNorm (optionally emit row L2 norm) ----------
// grid: MROWS, 128 threads (each owns 4 consecutive cols).
__global__ void ln_residual(const float* __restrict__ A, const float* __restrict__ Bin,
                            const float* __restrict__ gam, const float* __restrict__ bet,
                            float* __restrict__ Out, float* __restrict__ norms)
{
    const int row = blockIdx.x, tid = threadIdx.x;
    __shared__ float sh[4];
    const size_t off = (size_t)row * D_HID + tid * 4;
    float4 a = *(const float4*)(A + off);
    float4 b = *(const float4*)(Bin + off);
    float x0 = a.x + b.x, x1 = a.y + b.y, x2 = a.z + b.z, x3 = a.w + b.w;

    float s = x0 + x1 + x2 + x3;
#pragma unroll
    for (int o = 16; o > 0; o >>= 1) s += __shfl_xor_sync(0xffffffffu, s, o);
    if ((tid & 31) == 0) sh[tid >> 5] = s;
    __syncthreads();
    float stot = sh[0] + sh[1] + sh[2] + sh[3];
    __syncthreads();

    float q = x0 * x0 + x1 * x1 + x2 * x2 + x3 * x3;
#pragma unroll
    for (int o = 16; o > 0; o >>= 1) q += __shfl_xor_sync(0xffffffffu, q, o);
    if ((tid & 31) == 0) sh[tid >> 5] = q;
    __syncthreads();
    float qtot = sh[0] + sh[1] + sh[2] + sh[3];
    __syncthreads();

    float mu = stot * (1.0f / D_HID);
    float var = qtot * (1.0f / D_HID) - mu * mu;
    float rstd = rsqrtf(var + 1e-5f);
    float4 g4 = *(const float4*)(gam + tid * 4);
    float4 b4 = *(const float4*)(bet + tid * 4);
    float y0 = (x0 - mu) * rstd * g4.x + b4.x;
    float y1 = (x1 - mu) * rstd * g4.y + b4.y;
    float y2 = (x2 - mu) * rstd * g4.z + b4.z;
    float y3 = (x3 - mu) * rstd * g4.w + b4.w;
    float4 o4; o4.x = y0; o4.y = y1; o4.z = y2; o4.w = y3;
    *(float4*)(Out + off) = o4;

    if (norms) {
        float n = y0 * y0 + y1 * y1 + y2 * y2 + y3 * y3;
#pragma unroll
        for (int o = 16; o > 0; o >>= 1) n += __shfl_xor_sync(0xffffffffu, n, o);
        if ((tid & 31) == 0) sh[tid >> 5] = n;
        __syncthreads();
        if (tid == 0) norms[row] = sqrtf(sh[0] + sh[1] + sh[2] + sh[3]);
    }
}

// ---------------- softmax(norm)-weighted pooling -------------------------------
// grid: BATCH, 256 threads.
__global__ void pool_kernel(const float* __restrict__ X, const float* __restrict__ norms,
                            float* __restrict__ pooled)
{
    const int b = blockIdx.x, tid = threadIdx.x;
    __shared__ float w[SEQ];
    __shared__ float sh[8];

    float mx = -1e30f;
    for (int t = tid; t < SEQ; t += 256) mx = fmaxf(mx, norms[b * SEQ + t]);
#pragma unroll
    for (int o = 16; o > 0; o >>= 1) mx = fmaxf(mx, __shfl_xor_sync(0xffffffffu, mx, o));
    if ((tid & 31) == 0) sh[tid >> 5] = mx;
    __syncthreads();
    float mtot = -1e30f;
#pragma unroll
    for (int i = 0; i < 8; i++) mtot = fmaxf(mtot, sh[i]);
    __syncthreads();

    float sum = 0.f;
    for (int t = tid; t < SEQ; t += 256) {
        float e = expf(norms[b * SEQ + t] - mtot);
        w[t] = e;
        sum += e;
    }
#pragma unroll
    for (int o = 16; o > 0; o >>= 1) sum += __shfl_xor_sync(0xffffffffu, sum, o);
    if ((tid & 31) == 0) sh[tid >> 5] = sum;
    __syncthreads();
    float stot = 0.f;
#pragma unroll
    for (int i = 0; i < 8; i++) stot += sh[i];
    float inv = 1.0f / stot;
    __syncthreads();

    for (int d = tid; d < D_HID; d += 256) {
        float acc = 0.f;
        for (int t = 0; t < SEQ; t++)
            acc += w[t] * X[((size_t)b * SEQ + t) * D_HID + d];
        pooled[b * D_HID + d] = acc * inv;
    }
}

// ---------------- classifier: relu(pooled@fc1^T+b1)@fc2^T+b2 -------------------
// grid: BATCH, 256 threads.
__global__ void cls_kernel(const float* __restrict__ pooled,
                           const float* __restrict__ w1, const float* __restrict__ b1,
                           const float* __restrict__ w2, const float* __restrict__ b2,
                           float* __restrict__ out)
{
    const int b = blockIdx.x, tid = threadIdx.x;
    __shared__ float hb[256];
    float acc = b1[tid];
    const float* p  = pooled + b * D_HID;
    const float* wr = w1 + (size_t)tid * D_HID;
    for (int k = 0; k < D_HID; k += 4) {
        float4 pv = *(const float4*)(p + k);
        float4 wv = *(const float4*)(wr + k);
        acc += pv.x * wv.x + pv.y * wv.y + pv.z * wv.z + pv.w * wv.w;
    }
    hb[tid] = fmaxf(acc, 0.f);
    __syncthreads();
    if (tid < 2) {
        float a = b2[tid];
        for (int k = 0; k < 256; k++) a += hb[k] * w2[tid * 256 + k];
        out[b * 2 + tid] = a;
    }
}

// ---------------- host ----------------------------------------------------------
extern "C" void kernel_launch(void* const* d_in, const int* in_sizes, int n_in,
                              void* d_out, int out_size)
{
    const float* trg   = (const float*)d_in[0];
    const float* src   = (const float*)d_in[1];
    const float* ln_g  = (const float*)d_in[2];
    const float* ln_b  = (const float*)d_in[3];
    const float* wq    = (const float*)d_in[4];
    const float* bq    = (const float*)d_in[5];
    const float* wk    = (const float*)d_in[6];
    const float* bk    = (const float*)d_in[7];
    const float* wv    = (const float*)d_in[8];
    const float* bv    = (const float*)d_in[9];
    const float* wo    = (const float*)d_in[10];
    const float* bo    = (const float*)d_in[11];
    const float* pf1_w = (const float*)d_in[12];
    const float* pf1_b = (const float*)d_in[13];
    const float* pf2_w = (const float*)d_in[14];
    const float* pf2_b = (const float*)d_in[15];
    const float* fc1_w = (const float*)d_in[16];
    const float* fc1_b = (const float*)d_in[17];
    const float* fc2_w = (const float*)d_in[18];
    const float* fc2_b = (const float*)d_in[19];
    float* out = (float*)d_out;

    float *q, *k, *v, *ctx, *x1, *hid, *nr, *pl;
    cudaGetSymbolAddress((void**)&q,   g_q);
    cudaGetSymbolAddress((void**)&k,   g_k);
    cudaGetSymbolAddress((void**)&v,   g_v);
    cudaGetSymbolAddress((void**)&ctx, g_ctx);
    cudaGetSymbolAddress((void**)&x1,  g_x1);
    cudaGetSymbolAddress((void**)&hid, g_hid);
    cudaGetSymbolAddress((void**)&nr,  g_norms);
    cudaGetSymbolAddress((void**)&pl,  g_pooled);

    float* sa = k;    // k dead after flash_attn
    float* ff = v;    // v dead after flash_attn
    float* x2 = ctx;  // ctx dead after LN1 consumed... (ctx read only by wo GEMM; safe after that)

    dim3 g512(D_HID / 128, MROWS / 128);     // (4, 128)
    dim3 g2048(PFD / 128, MROWS / 128);      // (16, 128)

    sgemm_bias<<<g512, 256>>>(trg, wq, bq, q, MROWS, D_HID, D_HID, 0);
    sgemm_bias<<<g512, 256>>>(src, wk, bk, k, MROWS, D_HID, D_HID, 0);
    sgemm_bias<<<g512, 256>>>(src, wv, bv, v, MROWS, D_HID, D_HID, 0);

    flash_attn<<<dim3(SEQ / 64, NHEAD, BATCH), 256>>>(q, k, v, ctx);

    sgemm_bias<<<g512, 256>>>(ctx, wo, bo, sa, MROWS, D_HID, D_HID, 0);

    ln_residual<<<MROWS, 128>>>(trg, sa, ln_g, ln_b, x1, nullptr);

    sgemm_bias<<<g2048, 256>>>(x1, pf1_w, pf1_b, hid, MROWS, PFD, D_HID, 1);
    sgemm_bias<<<g512, 256>>>(hid, pf2_w, pf2_b, ff, MROWS, D_HID, PFD, 0);

    ln_residual<<<MROWS, 128>>>(x1, ff, ln_g, ln_b, x2, nr);

    pool_kernel<<<BATCH, 256>>>(x2, nr, pl);
    cls_kernel<<<BATCH, 256>>>(pl, fc1_w, fc1_b, fc2_w, fc2_b, out);
}

// round 4
// speedup vs baseline: 1.0711x; 1.0711x over previous
#include <cuda_runtime.h>
#include <math.h>

#define D_HID 512
#define SEQ   1024
#define BATCH 16
#define NHEAD 8
#define DHEAD 64
#define PFD   2048
#define MROWS (BATCH*SEQ)   /* 16384 */

#define SZ_MAT ((size_t)MROWS * D_HID)
#define SZ_H   ((size_t)MROWS * PFD)

// ---------------- scratch ----------------
__device__ float g_q[SZ_MAT];
__device__ float g_k[SZ_MAT];
__device__ float g_v[SZ_MAT];
__device__ float g_ctx[SZ_MAT];
__device__ float g_x1[SZ_MAT];
__device__ float g_hid[SZ_H];
__device__ float g_norms[MROWS];
__device__ float g_pooled[BATCH * D_HID];

// ---------------- tf32 helpers ----------------
__device__ __forceinline__ unsigned f2tf32(float x) {
    unsigned u;
    asm("cvt.rna.tf32.f32 %0, %1;" : "=r"(u) : "f"(x));
    return u;
}

// hi/lo split: x ~= hi + lo, both representable in tf32
__device__ __forceinline__ void split_tf32(float x, unsigned& hi, unsigned& lo) {
    hi = f2tf32(x);
    float hif = __uint_as_float(hi);
    lo = f2tf32(x - hif);
}

__device__ __forceinline__ void mma_tf32(float c[4], const unsigned a[4], const unsigned b[2]) {
    asm volatile(
        "mma.sync.aligned.m16n8k8.row.col.f32.tf32.tf32.f32 "
        "{%0,%1,%2,%3}, {%4,%5,%6,%7}, {%8,%9}, {%0,%1,%2,%3};\n"
        : "+f"(c[0]), "+f"(c[1]), "+f"(c[2]), "+f"(c[3])
        : "r"(a[0]), "r"(a[1]), "r"(a[2]), "r"(a[3]), "r"(b[0]), "r"(b[1]));
}

// ---------------- 3xTF32 GEMM: C[M,N] = A[M,K] @ W[N,K]^T + bias, opt ReLU ----
// Block 128x128, BK=16. 256 threads = 8 warps, warp tile 32(m) x 64(n).
// smem stride 20 -> conflict-free fragment loads.
// Precision: c += ah*bh + ah*bl + al*bh  (al*bl dropped, ~2.5e-7 rel).
__global__ __launch_bounds__(256) void gemm_3xtf32(
    const float* __restrict__ A, const float* __restrict__ W,
    const float* __restrict__ bias, float* __restrict__ C,
    int M, int N, int K, int doRelu)
{
    __shared__ unsigned Ah[128][20];
    __shared__ unsigned Al[128][20];
    __shared__ unsigned Bh[128][20];
    __shared__ unsigned Bl[128][20];

    const int tid  = threadIdx.x;
    const int lane = tid & 31, wid = tid >> 5;
    const int wm = (wid & 3) * 32;    // 4 warps along m
    const int wn = (wid >> 2) * 64;   // 2 warps along n
    const int grp = lane >> 2, qd = lane & 3;
    const int brow = blockIdx.y, bcol = blockIdx.x;

    const float* Ab = A + (size_t)brow * 128 * K;
    const float* Wb = W + (size_t)bcol * 128 * K;

    // global-load mapping: 128 rows x 4 float4 per row = 512 float4, 2/thread
    const int lrow = tid >> 2;        // 0..63, +64 for second
    const int lc4  = tid & 3;

    float c[2][8][4];
#pragma unroll
    for (int i = 0; i < 2; i++)
#pragma unroll
        for (int j = 0; j < 8; j++)
#pragma unroll
            for (int t = 0; t < 4; t++) c[i][j][t] = 0.f;

    float4 aReg[2], bReg[2];
#pragma unroll
    for (int r = 0; r < 2; r++) {
        int row = lrow + r * 64;
        aReg[r] = *(const float4*)(Ab + (size_t)row * K + lc4 * 4);
        bReg[r] = *(const float4*)(Wb + (size_t)row * K + lc4 * 4);
    }

    for (int k0 = 0; k0 < K; k0 += 16) {
        __syncthreads();
#pragma unroll
        for (int r = 0; r < 2; r++) {
            int row = lrow + r * 64;
            uint4 uah, ual, ubh, ubl;
            split_tf32(aReg[r].x, uah.x, ual.x);
            split_tf32(aReg[r].y, uah.y, ual.y);
            split_tf32(aReg[r].z, uah.z, ual.z);
            split_tf32(aReg[r].w, uah.w, ual.w);
            split_tf32(bReg[r].x, ubh.x, ubl.x);
            split_tf32(bReg[r].y, ubh.y, ubl.y);
            split_tf32(bReg[r].z, ubh.z, ubl.z);
            split_tf32(bReg[r].w, ubh.w, ubl.w);
            *(uint4*)&Ah[row][lc4 * 4] = uah;
            *(uint4*)&Al[row][lc4 * 4] = ual;
            *(uint4*)&Bh[row][lc4 * 4] = ubh;
            *(uint4*)&Bl[row][lc4 * 4] = ubl;
        }
        __syncthreads();

        if (k0 + 16 < K) {
#pragma unroll
            for (int r = 0; r < 2; r++) {
                int row = lrow + r * 64;
                aReg[r] = *(const float4*)(Ab + (size_t)row * K + k0 + 16 + lc4 * 4);
                bReg[r] = *(const float4*)(Wb + (size_t)row * K + k0 + 16 + lc4 * 4);
            }
        }

#pragma unroll
        for (int ks = 0; ks < 2; ks++) {
            const int kk = ks * 8;
            unsigned afh[2][4], afl[2][4], bfh[8][2], bfl[8][2];
#pragma unroll
            for (int i = 0; i < 2; i++) {
                int m = wm + i * 16 + grp;
                afh[i][0] = Ah[m][kk + qd];
                afh[i][1] = Ah[m + 8][kk + qd];
                afh[i][2] = Ah[m][kk + qd + 4];
                afh[i][3] = Ah[m + 8][kk + qd + 4];
                afl[i][0] = Al[m][kk + qd];
                afl[i][1] = Al[m + 8][kk + qd];
                afl[i][2] = Al[m][kk + qd + 4];
                afl[i][3] = Al[m + 8][kk + qd + 4];
            }
#pragma unroll
            for (int j = 0; j < 8; j++) {
                int n = wn + j * 8 + grp;
                bfh[j][0] = Bh[n][kk + qd];
                bfh[j][1] = Bh[n][kk + qd + 4];
                bfl[j][0] = Bl[n][kk + qd];
                bfl[j][1] = Bl[n][kk + qd + 4];
            }
#pragma unroll
            for (int i = 0; i < 2; i++)
#pragma unroll
                for (int j = 0; j < 8; j++) {
                    mma_tf32(c[i][j], afh[i], bfl[j]);   // hi*lo
                    mma_tf32(c[i][j], afl[i], bfh[j]);   // lo*hi
                    mma_tf32(c[i][j], afh[i], bfh[j]);   // hi*hi (last: biggest term)
                }
        }
    }

    // epilogue: bias + optional relu, float2 stores
#pragma unroll
    for (int j = 0; j < 8; j++) {
        int col = bcol * 128 + wn + j * 8 + qd * 2;
        float b0 = bias[col], b1 = bias[col + 1];
#pragma unroll
        for (int i = 0; i < 2; i++) {
            int row = brow * 128 + wm + i * 16 + grp;
            float v0 = c[i][j][0] + b0;
            float v1 = c[i][j][1] + b1;
            float v2 = c[i][j][2] + b0;
            float v3 = c[i][j][3] + b1;
            if (doRelu) {
                v0 = fmaxf(v0, 0.f); v1 = fmaxf(v1, 0.f);
                v2 = fmaxf(v2, 0.f); v3 = fmaxf(v3, 0.f);
            }
            float2 p0; p0.x = v0; p0.y = v1;
            float2 p1; p1.x = v2; p1.y = v3;
            *(float2*)(C + (size_t)row * N + col)       = p0;
            *(float2*)(C + (size_t)(row + 8) * N + col) = p1;
        }
    }
}

// ---------------- Flash attention (fp32 SIMT, unchanged) ------------------
__global__ __launch_bounds__(256) void flash_attn(
    const float* __restrict__ Q, const float* __restrict__ Kg,
    const float* __restrict__ Vg, float* __restrict__ O)
{
    __shared__ float qs[64][65];
    __shared__ float ks[32][65];
    __shared__ float vs[32][65];
    __shared__ float ss[64][33];
    __shared__ float m_s[64], l_s[64], alpha_s[64];

    const int tid = threadIdx.x;
    const int qt = blockIdx.x, hh = blockIdx.y, b = blockIdx.z;
    const size_t base = ((size_t)b * SEQ) * D_HID + hh * DHEAD;

#pragma unroll
    for (int rp = 0; rp < 4; rp++) {
        int f = tid + rp * 256;
        int row = f >> 4, c4 = f & 15;
        float4 v4 = *(const float4*)(Q + base + (size_t)(qt * 64 + row) * D_HID + c4 * 4);
        qs[row][c4 * 4 + 0] = v4.x; qs[row][c4 * 4 + 1] = v4.y;
        qs[row][c4 * 4 + 2] = v4.z; qs[row][c4 * 4 + 3] = v4.w;
    }
    if (tid < 64) { m_s[tid] = -1e30f; l_s[tid] = 0.f; }

    float acc[16];
#pragma unroll
    for (int i = 0; i < 16; i++) acc[i] = 0.f;

    const int r = tid >> 2;
    const int dl = tid & 3;

    for (int kt = 0; kt < SEQ / 32; kt++) {
        __syncthreads();
#pragma unroll
        for (int rp = 0; rp < 2; rp++) {
            int f = tid + rp * 256;
            int row = f >> 4, c4 = f & 15;
            size_t goff = base + (size_t)(kt * 32 + row) * D_HID + c4 * 4;
            float4 kv = *(const float4*)(Kg + goff);
            float4 vv = *(const float4*)(Vg + goff);
            ks[row][c4 * 4 + 0] = kv.x; ks[row][c4 * 4 + 1] = kv.y;
            ks[row][c4 * 4 + 2] = kv.z; ks[row][c4 * 4 + 3] = kv.w;
            vs[row][c4 * 4 + 0] = vv.x; vs[row][c4 * 4 + 1] = vv.y;
            vs[row][c4 * 4 + 2] = vv.z; vs[row][c4 * 4 + 3] = vv.w;
        }
        __syncthreads();

        {
            const int j0 = dl * 8;
            float sreg[8];
#pragma unroll
            for (int jj = 0; jj < 8; jj++) sreg[jj] = 0.f;
            for (int d = 0; d < 64; d++) {
                float qv = qs[r][d];
#pragma unroll
                for (int jj = 0; jj < 8; jj++) sreg[jj] += qv * ks[j0 + jj][d];
            }
#pragma unroll
            for (int jj = 0; jj < 8; jj++) ss[r][j0 + jj] = sreg[jj] * 0.125f;
        }
        __syncthreads();

        if (tid < 64) {
            float m_old = m_s[tid];
            float mt = m_old;
#pragma unroll
            for (int j = 0; j < 32; j++) mt = fmaxf(mt, ss[tid][j]);
            float alpha = expf(m_old - mt);
            float lsum = 0.f;
#pragma unroll
            for (int j = 0; j < 32; j++) {
                float p = expf(ss[tid][j] - mt);
                ss[tid][j] = p;
                lsum += p;
            }
            l_s[tid] = l_s[tid] * alpha + lsum;
            m_s[tid] = mt;
            alpha_s[tid] = alpha;
        }
        __syncthreads();

        {
            float al = alpha_s[r];
#pragma unroll
            for (int i = 0; i < 16; i++) acc[i] *= al;
            for (int j = 0; j < 32; j++) {
                float p = ss[r][j];
#pragma unroll
                for (int i = 0; i < 16; i++) acc[i] += p * vs[j][dl + 4 * i];
            }
        }
    }
    __syncthreads();
    float linv = 1.0f / l_s[r];
#pragma unroll
    for (int i = 0; i < 16; i++)
        O[base + (size_t)(qt * 64 + r) * D_HID + dl + 4 * i] = acc[i] * linv;
}

// ---------------- residual + LayerNorm ----------
__global__ void ln_residual(const float* __restrict__ A, const float* __restrict__ Bin,
                            const float* __restrict__ gam, const float* __restrict__ bet,
                            float* __restrict__ Out, float* __restrict__ norms)
{
    const int row = blockIdx.x, tid = threadIdx.x;
    __shared__ float sh[4];
    const size_t off = (size_t)row * D_HID + tid * 4;
    float4 a = *(const float4*)(A + off);
    float4 b = *(const float4*)(Bin + off);
    float x0 = a.x + b.x, x1 = a.y + b.y, x2 = a.z + b.z, x3 = a.w + b.w;

    float s = x0 + x1 + x2 + x3;
#pragma unroll
    for (int o = 16; o > 0; o >>= 1) s += __shfl_xor_sync(0xffffffffu, s, o);
    if ((tid & 31) == 0) sh[tid >> 5] = s;
    __syncthreads();
    float stot = sh[0] + sh[1] + sh[2] + sh[3];
    __syncthreads();

    float q = x0 * x0 + x1 * x1 + x2 * x2 + x3 * x3;
#pragma unroll
    for (int o = 16; o > 0; o >>= 1) q += __shfl_xor_sync(0xffffffffu, q, o);
    if ((tid & 31) == 0) sh[tid >> 5] = q;
    __syncthreads();
    float qtot = sh[0] + sh[1] + sh[2] + sh[3];
    __syncthreads();

    float mu = stot * (1.0f / D_HID);
    float var = qtot * (1.0f / D_HID) - mu * mu;
    float rstd = rsqrtf(var + 1e-5f);
    float4 g4 = *(const float4*)(gam + tid * 4);
    float4 b4 = *(const float4*)(bet + tid * 4);
    float y0 = (x0 - mu) * rstd * g4.x + b4.x;
    float y1 = (x1 - mu) * rstd * g4.y + b4.y;
    float y2 = (x2 - mu) * rstd * g4.z + b4.z;
    float y3 = (x3 - mu) * rstd * g4.w + b4.w;
    float4 o4; o4.x = y0; o4.y = y1; o4.z = y2; o4.w = y3;
    *(float4*)(Out + off) = o4;

    if (norms) {
        float n = y0 * y0 + y1 * y1 + y2 * y2 + y3 * y3;
#pragma unroll
        for (int o = 16; o > 0; o >>= 1) n += __shfl_xor_sync(0xffffffffu, n, o);
        if ((tid & 31) == 0) sh[tid >> 5] = n;
        __syncthreads();
        if (tid == 0) norms[row] = sqrtf(sh[0] + sh[1] + sh[2] + sh[3]);
    }
}

// ---------------- softmax(norm)-weighted pooling ----------------
__global__ void pool_kernel(const float* __restrict__ X, const float* __restrict__ norms,
                            float* __restrict__ pooled)
{
    const int b = blockIdx.x, tid = threadIdx.x;
    __shared__ float w[SEQ];
    __shared__ float sh[8];

    float mx = -1e30f;
    for (int t = tid; t < SEQ; t += 256) mx = fmaxf(mx, norms[b * SEQ + t]);
#pragma unroll
    for (int o = 16; o > 0; o >>= 1) mx = fmaxf(mx, __shfl_xor_sync(0xffffffffu, mx, o));
    if ((tid & 31) == 0) sh[tid >> 5] = mx;
    __syncthreads();
    float mtot = -1e30f;
#pragma unroll
    for (int i = 0; i < 8; i++) mtot = fmaxf(mtot, sh[i]);
    __syncthreads();

    float sum = 0.f;
    for (int t = tid; t < SEQ; t += 256) {
        float e = expf(norms[b * SEQ + t] - mtot);
        w[t] = e;
        sum += e;
    }
#pragma unroll
    for (int o = 16; o > 0; o >>= 1) sum += __shfl_xor_sync(0xffffffffu, sum, o);
    if ((tid & 31) == 0) sh[tid >> 5] = sum;
    __syncthreads();
    float stot = 0.f;
#pragma unroll
    for (int i = 0; i < 8; i++) stot += sh[i];
    float inv = 1.0f / stot;
    __syncthreads();

    for (int d = tid; d < D_HID; d += 256) {
        float acc = 0.f;
        for (int t = 0; t < SEQ; t++)
            acc += w[t] * X[((size_t)b * SEQ + t) * D_HID + d];
        pooled[b * D_HID + d] = acc * inv;
    }
}

// ---------------- classifier ----------------
__global__ void cls_kernel(const float* __restrict__ pooled,
                           const float* __restrict__ w1, const float* __restrict__ b1,
                           const float* __restrict__ w2, const float* __restrict__ b2,
                           float* __restrict__ out)
{
    const int b = blockIdx.x, tid = threadIdx.x;
    __shared__ float hb[256];
    float acc = b1[tid];
    const float* p  = pooled + b * D_HID;
    const float* wr = w1 + (size_t)tid * D_HID;
    for (int k = 0; k < D_HID; k += 4) {
        float4 pv = *(const float4*)(p + k);
        float4 wv = *(const float4*)(wr + k);
        acc += pv.x * wv.x + pv.y * wv.y + pv.z * wv.z + pv.w * wv.w;
    }
    hb[tid] = fmaxf(acc, 0.f);
    __syncthreads();
    if (tid < 2) {
        float a = b2[tid];
        for (int k = 0; k < 256; k++) a += hb[k] * w2[tid * 256 + k];
        out[b * 2 + tid] = a;
    }
}

// ---------------- host ----------------
extern "C" void kernel_launch(void* const* d_in, const int* in_sizes, int n_in,
                              void* d_out, int out_size)
{
    const float* trg   = (const float*)d_in[0];
    const float* src   = (const float*)d_in[1];
    const float* ln_g  = (const float*)d_in[2];
    const float* ln_b  = (const float*)d_in[3];
    const float* wq    = (const float*)d_in[4];
    const float* bq    = (const float*)d_in[5];
    const float* wk    = (const float*)d_in[6];
    const float* bk    = (const float*)d_in[7];
    const float* wv    = (const float*)d_in[8];
    const float* bv    = (const float*)d_in[9];
    const float* wo    = (const float*)d_in[10];
    const float* bo    = (const float*)d_in[11];
    const float* pf1_w = (const float*)d_in[12];
    const float* pf1_b = (const float*)d_in[13];
    const float* pf2_w = (const float*)d_in[14];
    const float* pf2_b = (const float*)d_in[15];
    const float* fc1_w = (const float*)d_in[16];
    const float* fc1_b = (const float*)d_in[17];
    const float* fc2_w = (const float*)d_in[18];
    const float* fc2_b = (const float*)d_in[19];
    float* out = (float*)d_out;

    float *q, *k, *v, *ctx, *x1, *hid, *nr, *pl;
    cudaGetSymbolAddress((void**)&q,   g_q);
    cudaGetSymbolAddress((void**)&k,   g_k);
    cudaGetSymbolAddress((void**)&v,   g_v);
    cudaGetSymbolAddress((void**)&ctx, g_ctx);
    cudaGetSymbolAddress((void**)&x1,  g_x1);
    cudaGetSymbolAddress((void**)&hid, g_hid);
    cudaGetSymbolAddress((void**)&nr,  g_norms);
    cudaGetSymbolAddress((void**)&pl,  g_pooled);

    float* sa = k;    // k dead after flash_attn
    float* ff = v;    // v dead after flash_attn
    float* x2 = ctx;  // ctx dead after wo GEMM

    dim3 g512(D_HID / 128, MROWS / 128);     // (4, 128)
    dim3 g2048(PFD / 128, MROWS / 128);      // (16, 128)

    gemm_3xtf32<<<g512, 256>>>(trg, wq, bq, q, MROWS, D_HID, D_HID, 0);
    gemm_3xtf32<<<g512, 256>>>(src, wk, bk, k, MROWS, D_HID, D_HID, 0);
    gemm_3xtf32<<<g512, 256>>>(src, wv, bv, v, MROWS, D_HID, D_HID, 0);

    flash_attn<<<dim3(SEQ / 64, NHEAD, BATCH), 256>>>(q, k, v, ctx);

    gemm_3xtf32<<<g512, 256>>>(ctx, wo, bo, sa, MROWS, D_HID, D_HID, 0);

    ln_residual<<<MROWS, 128>>>(trg, sa, ln_g, ln_b, x1, nullptr);

    gemm_3xtf32<<<g2048, 256>>>(x1, pf1_w, pf1_b, hid, MROWS, PFD, D_HID, 1);
    gemm_3xtf32<<<g512, 256>>>(hid, pf2_w, pf2_b, ff, MROWS, D_HID, PFD, 0);

    ln_residual<<<MROWS, 128>>>(x1, ff, ln_g, ln_b, x2, nr);

    pool_kernel<<<BATCH, 256>>>(x2, nr, pl);
    cls_kernel<<<BATCH, 256>>>(pl, fc1_w, fc1_b, fc2_w, fc2_b, out);
}